// round 15
// baseline (speedup 1.0000x reference)
#include <cuda_runtime.h>
#include <cstdint>
#include <cstddef>

// ---------------- problem constants ----------------
#define NN     50000
#define NE     500000
#define DNODE  64
#define DEDGE  8
#define DIN    72
#define HMSG   128
#define DMSG   64
#define HUPD   64
#define DOUT   32
#define HTEN   32

typedef unsigned long long ull;

// ---------------- device scratch ----------------
__device__ float g_aggr[(size_t)NN * DMSG];
__device__ float g_cnt[NN];
__device__ float g_y[(size_t)NN * HMSG];     // y = x @ Wm1[0:64]  (25.6 MB)
__device__ int   g_idx64;

// ---------------- packed f32x2 helpers ----------------
__device__ __forceinline__ ull fma2(ull a, ull b, ull c) {
    ull d; asm("fma.rn.f32x2 %0, %1, %2, %3;" : "=l"(d) : "l"(a), "l"(b), "l"(c));
    return d;
}
__device__ __forceinline__ ull dup2(float x) {
    ull d; asm("mov.b64 %0, {%1, %1};" : "=l"(d) : "f"(x)); return d;
}
__device__ __forceinline__ float2 unpack2(ull v) {
    float2 r; asm("mov.b64 {%0, %1}, %2;" : "=f"(r.x), "=f"(r.y) : "l"(v)); return r;
}
__device__ __forceinline__ void red_add_v2(float* addr, float a, float b) {
    asm volatile("red.global.add.v2.f32 [%0], {%1, %2};"
                 :: "l"(addr), "f"(a), "f"(b) : "memory");
}
__device__ __forceinline__ void red_add_f32(float* addr, float v) {
    asm volatile("red.global.add.f32 [%0], %1;"
                 :: "l"(addr), "f"(v) : "memory");
}

// ---------------- init ----------------
__global__ void init_kernel(const void* __restrict__ ei) {
    size_t tid    = (size_t)blockIdx.x * blockDim.x + threadIdx.x;
    size_t stride = (size_t)gridDim.x * blockDim.x;
    for (size_t i = tid; i < (size_t)NN * DMSG; i += stride) g_aggr[i] = 0.f;
    for (size_t i = tid; i < (size_t)NN; i += stride)        g_cnt[i]  = 0.f;
    if (tid == 0) {
        const unsigned long long* p = (const unsigned long long*)ei;
        int is64 = 1;
        for (int k = 0; k < 64; k++)
            if (p[k] >= (unsigned long long)NN) { is64 = 0; break; }
        g_idx64 = is64;
    }
}

// ---------------- precompute y = x @ Wm1[0:64,:]  ----------------
#define PY_NW 16
#define PYOFF_W 0
#define PYOFF_X (PYOFF_W + DNODE*HMSG)
#define PY_SMEM_FLOATS (PYOFF_X + PY_NW*2*DNODE)

__global__ void __launch_bounds__(PY_NW * 32, 1)
precompute_y_kernel(const float* __restrict__ x, const float* __restrict__ Wm1)
{
    extern __shared__ float sm[];
    for (int i = threadIdx.x; i < DNODE*HMSG; i += blockDim.x) sm[PYOFF_W+i] = Wm1[i];
    __syncthreads();

    const int lane = threadIdx.x & 31;
    const int warp = threadIdx.x >> 5;
    float* xs_w = sm + PYOFF_X + warp * (2*DNODE);

    const int gw     = blockIdx.x * PY_NW + warp;
    const int nwarps = gridDim.x * PY_NW;

    for (int n = gw; n < NN; n += nwarps) {
        const float2 xv = *(const float2*)(x + (size_t)n*DNODE + 2*lane);
        float4 d; d.x = xv.x; d.y = xv.x; d.z = xv.y; d.w = xv.y;
        *(float4*)(xs_w + 4*lane) = d;
        __syncwarp();

        ull a0 = 0ULL, a1 = 0ULL;
        #pragma unroll 8
        for (int i = 0; i < DNODE; i++) {
            ulonglong2 w2 = *(const ulonglong2*)(sm + PYOFF_W + i*HMSG + 4*lane);
            ull vv = *(const ull*)(xs_w + 2*i);
            a0 = fma2(vv, w2.x, a0);
            a1 = fma2(vv, w2.y, a1);
        }
        ulonglong2 o; o.x = a0; o.y = a1;
        *(ulonglong2*)(g_y + (size_t)n*HMSG + 4*lane) = o;
        __syncwarp();
    }
}

// ---------------- edge kernel: B=6 edges/warp, 20 warps, dup'd Wm2 ----------
#define EK_NW 20
#define EK_B  6
#define EK_B2 (EK_B/2)
#define HCHUNK 32
#define NCHUNK (HMSG/HCHUNK)   // 4

#define OFF_WM1 0                                // 72*128   = 9216
#define OFF_W2D (OFF_WM1 + DIN*HMSG)             // dup'd Wm2: 128*64*2 = 16384
#define OFF_WT1 (OFF_W2D + HMSG*DMSG*2)          // 25600 (d-pair transposed, 2048)
#define OFF_BM1 (OFF_WT1 + DMSG*HTEN)            // 27648
#define OFF_BM2 (OFF_BM1 + HMSG)                 // 27776
#define OFF_BT1 (OFF_BM2 + DMSG)                 // 27840
#define OFF_WT2 (OFF_BT1 + HTEN)                 // 27872
#define OFF_BT2 (OFF_WT2 + HTEN)                 // 27904
#define OFF_EA  (OFF_BT2 + 4)                    // 27908 (16B aligned)
#define OFF_MS  (OFF_EA + EK_NW*EK_B*2*DEDGE)    // +20*96  = 29828
#define OFF_H   (OFF_MS + EK_NW*EK_B*2*DMSG)     // +20*768 = 45188
#define EK_SMEM_FLOATS (OFF_H + EK_NW*EK_B*2*HCHUNK) // +20*384 = 52868 fl (211.5KB)

__global__ void __launch_bounds__(EK_NW * 32, 1)
edge_kernel(const void* __restrict__ ei,
            const float* __restrict__ ea,
            const float* __restrict__ Wm1, const float* __restrict__ bm1,
            const float* __restrict__ Wm2, const float* __restrict__ bm2,
            const float* __restrict__ Wt1, const float* __restrict__ bt1,
            const float* __restrict__ Wt2, const float* __restrict__ bt2,
            float* __restrict__ e_out)
{
    extern __shared__ float sm[];
    for (int i = threadIdx.x; i < DIN*HMSG;  i += blockDim.x) sm[OFF_WM1+i] = Wm1[i];
    // Wm2 duplicated: w2d[j*128 + 2k] = w2d[j*128 + 2k+1] = Wm2[j*64 + k]
    for (int idx = threadIdx.x; idx < HMSG*DMSG; idx += blockDim.x) {
        int j = idx >> 6, k = idx & 63;
        float w = Wm2[idx];
        sm[OFF_W2D + j*128 + 2*k]     = w;
        sm[OFF_W2D + j*128 + 2*k + 1] = w;
    }
    // Wt1 d-pair transposed (as R14)
    for (int idx = threadIdx.x; idx < 32*16; idx += blockDim.x) {
        int s = idx >> 4, k = idx & 15;
        float* dst = sm + OFF_WT1 + s*64 + 4*k;
        dst[0] = Wt1[(2*s)*HTEN   + 2*k];
        dst[1] = Wt1[(2*s)*HTEN   + 2*k+1];
        dst[2] = Wt1[(2*s+1)*HTEN + 2*k];
        dst[3] = Wt1[(2*s+1)*HTEN + 2*k+1];
    }
    for (int i = threadIdx.x; i < HMSG; i += blockDim.x) sm[OFF_BM1+i] = bm1[i];
    for (int i = threadIdx.x; i < DMSG; i += blockDim.x) sm[OFF_BM2+i] = bm2[i];
    for (int i = threadIdx.x; i < HTEN; i += blockDim.x) {
        sm[OFF_BT1+i] = bt1[i];
        sm[OFF_WT2+i] = Wt2[i];
    }
    if (threadIdx.x == 0) sm[OFF_BT2] = bt2[0];
    __syncthreads();

    const int lane = threadIdx.x & 31;
    const int warp = threadIdx.x >> 5;
    const int half = lane >> 4;
    const int l16  = lane & 15;

    float* ea_w = sm + OFF_EA + warp * (EK_B * 2 * DEDGE);
    float* ms_w = sm + OFF_MS + warp * (EK_B * 2 * DMSG);
    float* h_w  = sm + OFF_H  + warp * (EK_B * 2 * HCHUNK);

    const float4 b1p  = *(const float4*)(sm + OFF_BM1 + 4*lane);
    const float4 b2p  = *(const float4*)(sm + OFF_BM2 + 4*l16);
    const float2 bt1p = *(const float2*)(sm + OFF_BT1 + 2*l16);
    const float2 wt2p = *(const float2*)(sm + OFF_WT2 + 2*l16);
    const float  bt2v = sm[OFF_BT2];
    const ull    NEG1 = dup2(-1.0f);

    const bool idx64 = (g_idx64 != 0);
    const long long* ei64 = (const long long*)ei;
    const int*       ei32 = (const int*)ei;

    const int gw     = blockIdx.x * EK_NW + warp;
    const int nwarps = gridDim.x * EK_NW;

    for (int base = gw * EK_B; base < NE; base += nwarps * EK_B) {
        int sr[EK_B], tg[EK_B];
        #pragma unroll
        for (int e = 0; e < EK_B; e++) {
            int id = base + e; if (id >= NE) id = NE - 1;   // tail clamp
            if (idx64) { sr[e] = (int)ei64[id]; tg[e] = (int)ei64[NE + id]; }
            else       { sr[e] = ei32[id];      tg[e] = ei32[NE + id]; }
        }

        // ---- stage duplicated edge attrs (24 active lanes) ----
        if (lane < 4*EK_B) {
            int e = lane >> 2, l4 = lane & 3;
            int id = base + e; if (id >= NE) id = NE - 1;
            float2 ev = *(const float2*)(ea + (size_t)id*DEDGE + 2*l4);
            float4 d; d.x = ev.x; d.y = ev.x; d.z = ev.y; d.w = ev.y;
            *(float4*)(ea_w + e*(2*DEDGE) + 4*l4) = d;
        }
        __syncwarp();

        // ---- layer 1 via precomputed y: z = y[t] - y[s] + Wm1[64:72]^T ea ----
        ull z[EK_B][2];
        #pragma unroll
        for (int e = 0; e < EK_B; e++) {
            ulonglong2 yt = *(const ulonglong2*)(g_y + (size_t)tg[e]*HMSG + 4*lane);
            ulonglong2 ys = *(const ulonglong2*)(g_y + (size_t)sr[e]*HMSG + 4*lane);
            z[e][0] = fma2(ys.x, NEG1, yt.x);
            z[e][1] = fma2(ys.y, NEG1, yt.y);
        }
        #pragma unroll
        for (int i = 0; i < DEDGE; i++) {
            ulonglong2 w2 = *(const ulonglong2*)(sm + OFF_WM1 + (DNODE+i)*HMSG + 4*lane);
            #pragma unroll
            for (int e = 0; e < EK_B; e++) {
                ull vv = *(const ull*)(ea_w + e*(2*DEDGE) + 2*i);
                z[e][0] = fma2(vv, w2.x, z[e][0]);
                z[e][1] = fma2(vv, w2.y, z[e][1]);
            }
        }

        // ---- layer 2 in four 32-j chunks; chunk c written by lanes 8c..8c+7 ----
        ull acc[EK_B2][4];
        #pragma unroll
        for (int es = 0; es < EK_B2; es++)
            #pragma unroll
            for (int k = 0; k < 4; k++) acc[es][k] = 0ULL;

        const float* hp0 = h_w + (0 + half)*(2*HCHUNK);
        const float* hp1 = h_w + (2 + half)*(2*HCHUNK);
        const float* hp2 = h_w + (4 + half)*(2*HCHUNK);

        #pragma unroll
        for (int c = 0; c < NCHUNK; c++) {
            if ((lane >> 3) == c) {
                const int l8 = lane & 7;
                #pragma unroll
                for (int e = 0; e < EK_B; e++) {
                    float2 za = unpack2(z[e][0]);
                    float2 zb = unpack2(z[e][1]);
                    float4 h0, h1;
                    h0.x = fmaxf(za.x + b1p.x, 0.f); h0.y = fmaxf(b1p.x - za.x, 0.f);
                    h0.z = fmaxf(za.y + b1p.y, 0.f); h0.w = fmaxf(b1p.y - za.y, 0.f);
                    h1.x = fmaxf(zb.x + b1p.z, 0.f); h1.y = fmaxf(b1p.z - zb.x, 0.f);
                    h1.z = fmaxf(zb.y + b1p.w, 0.f); h1.w = fmaxf(b1p.w - zb.y, 0.f);
                    *(float4*)(h_w + e*(2*HCHUNK) + 8*l8)     = h0; // j pair {f,b}
                    *(float4*)(h_w + e*(2*HCHUNK) + 8*l8 + 4) = h1;
                }
            }
            __syncwarp();

            #pragma unroll 2
            for (int jj = 0; jj < HCHUNK; jj += 2) {
                const int j0 = c*HCHUNK + jj;
                const float* wr0 = sm + OFF_W2D + j0*128 + 8*l16;
                const float* wr1 = wr0 + 128;
                ulonglong2 wA0 = *(const ulonglong2*)wr0;        // dup'd outs 0,1
                ulonglong2 wA1 = *(const ulonglong2*)(wr0 + 4);  // dup'd outs 2,3
                ulonglong2 wB0 = *(const ulonglong2*)wr1;
                ulonglong2 wB1 = *(const ulonglong2*)(wr1 + 4);
                ulonglong2 hA = *(const ulonglong2*)(hp0 + 2*jj); // {f0,b0,f1,b1}
                ulonglong2 hB = *(const ulonglong2*)(hp1 + 2*jj);
                ulonglong2 hC = *(const ulonglong2*)(hp2 + 2*jj);
                acc[0][0] = fma2(hA.x, wA0.x, acc[0][0]);
                acc[0][1] = fma2(hA.x, wA0.y, acc[0][1]);
                acc[0][2] = fma2(hA.x, wA1.x, acc[0][2]);
                acc[0][3] = fma2(hA.x, wA1.y, acc[0][3]);
                acc[1][0] = fma2(hB.x, wA0.x, acc[1][0]);
                acc[1][1] = fma2(hB.x, wA0.y, acc[1][1]);
                acc[1][2] = fma2(hB.x, wA1.x, acc[1][2]);
                acc[1][3] = fma2(hB.x, wA1.y, acc[1][3]);
                acc[2][0] = fma2(hC.x, wA0.x, acc[2][0]);
                acc[2][1] = fma2(hC.x, wA0.y, acc[2][1]);
                acc[2][2] = fma2(hC.x, wA1.x, acc[2][2]);
                acc[2][3] = fma2(hC.x, wA1.y, acc[2][3]);
                acc[0][0] = fma2(hA.y, wB0.x, acc[0][0]);
                acc[0][1] = fma2(hA.y, wB0.y, acc[0][1]);
                acc[0][2] = fma2(hA.y, wB1.x, acc[0][2]);
                acc[0][3] = fma2(hA.y, wB1.y, acc[0][3]);
                acc[1][0] = fma2(hB.y, wB0.x, acc[1][0]);
                acc[1][1] = fma2(hB.y, wB0.y, acc[1][1]);
                acc[1][2] = fma2(hB.y, wB1.x, acc[1][2]);
                acc[1][3] = fma2(hB.y, wB1.y, acc[1][3]);
                acc[2][0] = fma2(hC.y, wB0.x, acc[2][0]);
                acc[2][1] = fma2(hC.y, wB0.y, acc[2][1]);
                acc[2][2] = fma2(hC.y, wB1.x, acc[2][2]);
                acc[2][3] = fma2(hC.y, wB1.y, acc[2][3]);
            }
            __syncwarp();
        }

        // ---- bias+relu, RED scatter (tail-predicated), m_sym (dup'd) ----
        #pragma unroll
        for (int es = 0; es < EK_B2; es++) {
            const int e = 2*es + half;
            const bool valid = (base + e) < NE;
            const int t = tg[e];
            const int s = sr[e];
            float2 a0 = unpack2(acc[es][0]);
            float2 a1 = unpack2(acc[es][1]);
            float2 a2 = unpack2(acc[es][2]);
            float2 a3 = unpack2(acc[es][3]);
            float f0 = fmaxf(a0.x + b2p.x, 0.f), g0 = fmaxf(a0.y + b2p.x, 0.f);
            float f1 = fmaxf(a1.x + b2p.y, 0.f), g1 = fmaxf(a1.y + b2p.y, 0.f);
            float f2 = fmaxf(a2.x + b2p.z, 0.f), g2 = fmaxf(a2.y + b2p.z, 0.f);
            float f3 = fmaxf(a3.x + b2p.w, 0.f), g3 = fmaxf(a3.y + b2p.w, 0.f);
            if (valid) {
                red_add_v2(g_aggr + (size_t)t*DMSG + 4*l16,     f0, f1);
                red_add_v2(g_aggr + (size_t)t*DMSG + 4*l16 + 2, f2, f3);
                red_add_v2(g_aggr + (size_t)s*DMSG + 4*l16,     g0, g1);
                red_add_v2(g_aggr + (size_t)s*DMSG + 4*l16 + 2, g2, g3);
            }
            float s0 = f0+g0, s1 = f1+g1, s2 = f2+g2, s3 = f3+g3;
            float4 svA; svA.x = s0; svA.y = s0; svA.z = s1; svA.w = s1;
            float4 svB; svB.x = s2; svB.y = s2; svB.z = s3; svB.w = s3;
            *(float4*)(ms_w + e*(2*DMSG) + 8*l16)     = svA;
            *(float4*)(ms_w + e*(2*DMSG) + 8*l16 + 4) = svB;
        }
        if (lane < 2*EK_B) {
            int e = lane >> 1;
            if (base + e < NE) {
                int node = (lane & 1) ? sr[e] : tg[e];
                red_add_f32(g_cnt + node, 1.f);
            }
        }
        __syncwarp();

        // ---- tension MLP: paired-transposed Wt1, all edges in one d-loop ----
        ull tac[EK_B2];
        #pragma unroll
        for (int p = 0; p < EK_B2; p++) tac[p] = 0ULL;
        #pragma unroll 4
        for (int s = 0; s < 32; s++) {
            ulonglong2 w = *(const ulonglong2*)(sm + OFF_WT1 + s*64 + 4*l16);
            #pragma unroll
            for (int p = 0; p < EK_B2; p++) {
                const float* msp = ms_w + (2*p + half)*(2*DMSG);
                ulonglong2 mv = *(const ulonglong2*)(msp + 4*s);
                tac[p] = fma2(mv.x, w.x, tac[p]);
                tac[p] = fma2(mv.y, w.y, tac[p]);
            }
        }
        #pragma unroll
        for (int p = 0; p < EK_B2; p++) {
            float2 ac = unpack2(tac[p]);
            float h0 = fmaxf(ac.x + bt1p.x, 0.f);
            float h1 = fmaxf(ac.y + bt1p.y, 0.f);
            float c  = h0*wt2p.x + h1*wt2p.y;
            #pragma unroll
            for (int off = 8; off > 0; off >>= 1)
                c += __shfl_xor_sync(0xffffffffu, c, off);
            if (l16 == 0 && (base + 2*p + half) < NE)
                e_out[base + 2*p + half] = c + bt2v;
        }
        __syncwarp();
    }
}

// ---------------- node kernel v2 (unchanged from R14) ----------------
#define NK_NW 16
#define NB    4
#define NOFF_W1T 0
#define NOFF_W2T (NOFF_W1T + 8192)
#define NOFF_BU1 (NOFF_W2T + 2048)
#define NOFF_BU2 (NOFF_BU1 + HUPD)
#define NOFF_IN  (NOFF_BU2 + DOUT)
#define NOFF_H   (NOFF_IN + NK_NW*NB*(DNODE+DMSG))
#define NK_SMEM_FLOATS (NOFF_H + NK_NW*NB*HUPD)

__global__ void __launch_bounds__(NK_NW * 32, 1)
node_kernel(const float* __restrict__ x,
            const float* __restrict__ Wu1, const float* __restrict__ bu1,
            const float* __restrict__ Wu2, const float* __restrict__ bu2,
            float* __restrict__ x_out)
{
    extern __shared__ float sm[];
    for (int idx = threadIdx.x; idx < 64*64; idx += blockDim.x) {
        int s = idx >> 6, k = idx & 63;
        sm[NOFF_W1T + s*128 + 2*k]     = Wu1[(2*s)*HUPD   + k];
        sm[NOFF_W1T + s*128 + 2*k + 1] = Wu1[(2*s+1)*HUPD + k];
    }
    for (int idx = threadIdx.x; idx < 32*32; idx += blockDim.x) {
        int s = idx >> 5, o = idx & 31;
        sm[NOFF_W2T + s*64 + 2*o]     = Wu2[(2*s)*DOUT   + o];
        sm[NOFF_W2T + s*64 + 2*o + 1] = Wu2[(2*s+1)*DOUT + o];
    }
    for (int i = threadIdx.x; i < HUPD; i += blockDim.x) sm[NOFF_BU1+i] = bu1[i];
    for (int i = threadIdx.x; i < DOUT; i += blockDim.x) sm[NOFF_BU2+i] = bu2[i];
    __syncthreads();

    const int lane = threadIdx.x & 31;
    const int warp = threadIdx.x >> 5;
    float* in_w = sm + NOFF_IN + warp * (NB * 128);
    float* h_w  = sm + NOFF_H  + warp * (NB * HUPD);

    const float2 b1 = *(const float2*)(sm + NOFF_BU1 + 2*lane);
    const float  b2 = sm[NOFF_BU2 + lane];

    const int gw     = blockIdx.x * NK_NW + warp;
    const int nwarps = gridDim.x * NK_NW;

    for (int n0 = gw * NB; n0 < NN; n0 += nwarps * NB) {
        #pragma unroll
        for (int e = 0; e < NB; e++) {
            int n = n0 + e; if (n >= NN) n = NN - 1;
            float inv = 1.f / fmaxf(g_cnt[n], 1.f);
            float2 xv = *(const float2*)(x + (size_t)n*DNODE + 2*lane);
            float2 av = *(const float2*)(g_aggr + (size_t)n*DMSG + 2*lane);
            av.x *= inv; av.y *= inv;
            *(float2*)(in_w + e*128 + 2*lane)      = xv;
            *(float2*)(in_w + e*128 + 64 + 2*lane) = av;
        }
        __syncwarp();

        ull accA[NB], accB[NB];
        #pragma unroll
        for (int e = 0; e < NB; e++) { accA[e] = 0ULL; accB[e] = 0ULL; }

        #pragma unroll 8
        for (int s = 0; s < 64; s++) {
            ulonglong2 w = *(const ulonglong2*)(sm + NOFF_W1T + s*128 + 4*lane);
            #pragma unroll
            for (int e = 0; e < NB; e++) {
                ull vv = *(const ull*)(in_w + e*128 + 2*s);
                accA[e] = fma2(vv, w.x, accA[e]);
                accB[e] = fma2(vv, w.y, accB[e]);
            }
        }
        #pragma unroll
        for (int e = 0; e < NB; e++) {
            float2 a = unpack2(accA[e]);
            float2 b = unpack2(accB[e]);
            float2 h;
            h.x = fmaxf(a.x + a.y + b1.x, 0.f);
            h.y = fmaxf(b.x + b.y + b1.y, 0.f);
            *(float2*)(h_w + e*HUPD + 2*lane) = h;
        }
        __syncwarp();

        ull acc2[NB];
        #pragma unroll
        for (int e = 0; e < NB; e++) acc2[e] = 0ULL;
        #pragma unroll 8
        for (int s = 0; s < 32; s++) {
            ull w = *(const ull*)(sm + NOFF_W2T + s*64 + 2*lane);
            #pragma unroll
            for (int e = 0; e < NB; e++) {
                ull hv = *(const ull*)(h_w + e*HUPD + 2*s);
                acc2[e] = fma2(hv, w, acc2[e]);
            }
        }
        #pragma unroll
        for (int e = 0; e < NB; e++) {
            int n = n0 + e;
            if (n < NN) {
                float2 a = unpack2(acc2[e]);
                x_out[(size_t)n*DOUT + lane] = a.x + a.y + b2;
            }
        }
        __syncwarp();
    }
}

// ---------------- launch ----------------
extern "C" void kernel_launch(void* const* d_in, const int* in_sizes, int n_in,
                              void* d_out, int out_size)
{
    (void)in_sizes; (void)n_in; (void)out_size;
    const float* x   = (const float*)d_in[0];
    const void*  ei  =               d_in[1];
    const float* ea  = (const float*)d_in[2];
    const float* Wm1 = (const float*)d_in[3];
    const float* bm1 = (const float*)d_in[4];
    const float* Wm2 = (const float*)d_in[5];
    const float* bm2 = (const float*)d_in[6];
    const float* Wu1 = (const float*)d_in[7];
    const float* bu1 = (const float*)d_in[8];
    const float* Wu2 = (const float*)d_in[9];
    const float* bu2 = (const float*)d_in[10];
    const float* Wt1 = (const float*)d_in[11];
    const float* bt1 = (const float*)d_in[12];
    const float* Wt2 = (const float*)d_in[13];
    const float* bt2 = (const float*)d_in[14];

    float* x_out = (float*)d_out;
    float* e_out = x_out + (size_t)NN * DOUT;

    int nsm = 148;
    cudaDeviceGetAttribute(&nsm, cudaDevAttrMultiProcessorCount, 0);

    cudaFuncSetAttribute(precompute_y_kernel, cudaFuncAttributeMaxDynamicSharedMemorySize,
                         PY_SMEM_FLOATS * (int)sizeof(float));
    cudaFuncSetAttribute(edge_kernel, cudaFuncAttributeMaxDynamicSharedMemorySize,
                         EK_SMEM_FLOATS * (int)sizeof(float));
    cudaFuncSetAttribute(node_kernel, cudaFuncAttributeMaxDynamicSharedMemorySize,
                         NK_SMEM_FLOATS * (int)sizeof(float));

    init_kernel<<<1024, 256>>>(ei);
    precompute_y_kernel<<<nsm, PY_NW * 32, PY_SMEM_FLOATS * sizeof(float)>>>(x, Wm1);
    edge_kernel<<<nsm, EK_NW * 32, EK_SMEM_FLOATS * sizeof(float)>>>(
        ei, ea, Wm1, bm1, Wm2, bm2, Wt1, bt1, Wt2, bt2, e_out);
    node_kernel<<<2*nsm, NK_NW * 32, NK_SMEM_FLOATS * sizeof(float)>>>(
        x, Wu1, bu1, Wu2, bu2, x_out);
}

// round 16
// speedup vs baseline: 1.1673x; 1.1673x over previous
#include <cuda_runtime.h>
#include <cstdint>
#include <cstddef>

// ---------------- problem constants ----------------
#define NN     50000
#define NE     500000
#define DNODE  64
#define DEDGE  8
#define DIN    72
#define HMSG   128
#define DMSG   64
#define HUPD   64
#define DOUT   32
#define HTEN   32

typedef unsigned long long ull;

// ---------------- device scratch ----------------
__device__ float g_aggr[(size_t)NN * DMSG];
__device__ float g_cnt[NN];
__device__ float g_y[(size_t)NN * HMSG];     // y = x @ Wm1[0:64]  (25.6 MB)
__device__ int   g_idx64;

// ---------------- packed f32x2 helpers ----------------
__device__ __forceinline__ ull fma2(ull a, ull b, ull c) {
    ull d; asm("fma.rn.f32x2 %0, %1, %2, %3;" : "=l"(d) : "l"(a), "l"(b), "l"(c));
    return d;
}
__device__ __forceinline__ ull dup2(float x) {
    ull d; asm("mov.b64 %0, {%1, %1};" : "=l"(d) : "f"(x)); return d;
}
__device__ __forceinline__ float2 unpack2(ull v) {
    float2 r; asm("mov.b64 {%0, %1}, %2;" : "=f"(r.x), "=f"(r.y) : "l"(v)); return r;
}
__device__ __forceinline__ void red_add_v2(float* addr, float a, float b) {
    asm volatile("red.global.add.v2.f32 [%0], {%1, %2};"
                 :: "l"(addr), "f"(a), "f"(b) : "memory");
}
__device__ __forceinline__ void red_add_f32(float* addr, float v) {
    asm volatile("red.global.add.f32 [%0], %1;"
                 :: "l"(addr), "f"(v) : "memory");
}

// ---------------- init ----------------
__global__ void init_kernel(const void* __restrict__ ei) {
    size_t tid    = (size_t)blockIdx.x * blockDim.x + threadIdx.x;
    size_t stride = (size_t)gridDim.x * blockDim.x;
    for (size_t i = tid; i < (size_t)NN * DMSG; i += stride) g_aggr[i] = 0.f;
    for (size_t i = tid; i < (size_t)NN; i += stride)        g_cnt[i]  = 0.f;
    if (tid == 0) {
        const unsigned long long* p = (const unsigned long long*)ei;
        int is64 = 1;
        for (int k = 0; k < 64; k++)
            if (p[k] >= (unsigned long long)NN) { is64 = 0; break; }
        g_idx64 = is64;
    }
}

// ---------------- precompute y = x @ Wm1[0:64,:]  ----------------
#define PY_NW 16
#define PYOFF_W 0
#define PYOFF_X (PYOFF_W + DNODE*HMSG)
#define PY_SMEM_FLOATS (PYOFF_X + PY_NW*2*DNODE)

__global__ void __launch_bounds__(PY_NW * 32, 1)
precompute_y_kernel(const float* __restrict__ x, const float* __restrict__ Wm1)
{
    extern __shared__ float sm[];
    for (int i = threadIdx.x; i < DNODE*HMSG; i += blockDim.x) sm[PYOFF_W+i] = Wm1[i];
    __syncthreads();

    const int lane = threadIdx.x & 31;
    const int warp = threadIdx.x >> 5;
    float* xs_w = sm + PYOFF_X + warp * (2*DNODE);

    const int gw     = blockIdx.x * PY_NW + warp;
    const int nwarps = gridDim.x * PY_NW;

    for (int n = gw; n < NN; n += nwarps) {
        const float2 xv = *(const float2*)(x + (size_t)n*DNODE + 2*lane);
        float4 d; d.x = xv.x; d.y = xv.x; d.z = xv.y; d.w = xv.y;
        *(float4*)(xs_w + 4*lane) = d;
        __syncwarp();

        ull a0 = 0ULL, a1 = 0ULL;
        #pragma unroll 8
        for (int i = 0; i < DNODE; i++) {
            ulonglong2 w2 = *(const ulonglong2*)(sm + PYOFF_W + i*HMSG + 4*lane);
            ull vv = *(const ull*)(xs_w + 2*i);
            a0 = fma2(vv, w2.x, a0);
            a1 = fma2(vv, w2.y, a1);
        }
        ulonglong2 o; o.x = a0; o.y = a1;
        *(ulonglong2*)(g_y + (size_t)n*HMSG + 4*lane) = o;
        __syncwarp();
    }
}

// ---------------- edge kernel: R14 skeleton (B=8, NW=16) + dup'd Wm2 --------
#define EK_NW 16
#define EK_B  8
#define HCHUNK 32
#define NCHUNK (HMSG/HCHUNK)   // 4

#define OFF_WM1 0                                // 72*128 = 9216
#define OFF_W2D (OFF_WM1 + DIN*HMSG)             // dup'd Wm2: 128*64*2 = 16384
#define OFF_WT1 (OFF_W2D + HMSG*DMSG*2)          // 25600 (d-pair transposed, 2048)
#define OFF_BM1 (OFF_WT1 + DMSG*HTEN)            // 27648
#define OFF_BM2 (OFF_BM1 + HMSG)                 // 27776
#define OFF_BT1 (OFF_BM2 + DMSG)                 // 27840
#define OFF_WT2 (OFF_BT1 + HTEN)                 // 27872
#define OFF_BT2 (OFF_WT2 + HTEN)                 // 27904
#define OFF_EA  (OFF_BT2 + 4)                    // 27908 (16B aligned)
#define OFF_MS  (OFF_EA + EK_NW*EK_B*2*DEDGE)    // +16*128  = 29956
#define OFF_H   (OFF_MS + EK_NW*EK_B*2*DMSG)     // +16*1024 = 46340
#define EK_SMEM_FLOATS (OFF_H + EK_NW*EK_B*2*HCHUNK) // +16*512 = 54532 fl (218KB)

__global__ void __launch_bounds__(EK_NW * 32, 1)
edge_kernel(const void* __restrict__ ei,
            const float* __restrict__ ea,
            const float* __restrict__ Wm1, const float* __restrict__ bm1,
            const float* __restrict__ Wm2, const float* __restrict__ bm2,
            const float* __restrict__ Wt1, const float* __restrict__ bt1,
            const float* __restrict__ Wt2, const float* __restrict__ bt2,
            float* __restrict__ e_out)
{
    extern __shared__ float sm[];
    for (int i = threadIdx.x; i < DIN*HMSG;  i += blockDim.x) sm[OFF_WM1+i] = Wm1[i];
    // Wm2 duplicated: w2d[j*128 + 2k] = w2d[j*128 + 2k+1] = Wm2[j*64 + k]
    for (int idx = threadIdx.x; idx < HMSG*DMSG; idx += blockDim.x) {
        int j = idx >> 6, k = idx & 63;
        float w = Wm2[idx];
        sm[OFF_W2D + j*128 + 2*k]     = w;
        sm[OFF_W2D + j*128 + 2*k + 1] = w;
    }
    // Wt1 d-pair transposed
    for (int idx = threadIdx.x; idx < 32*16; idx += blockDim.x) {
        int s = idx >> 4, k = idx & 15;
        float* dst = sm + OFF_WT1 + s*64 + 4*k;
        dst[0] = Wt1[(2*s)*HTEN   + 2*k];
        dst[1] = Wt1[(2*s)*HTEN   + 2*k+1];
        dst[2] = Wt1[(2*s+1)*HTEN + 2*k];
        dst[3] = Wt1[(2*s+1)*HTEN + 2*k+1];
    }
    for (int i = threadIdx.x; i < HMSG; i += blockDim.x) sm[OFF_BM1+i] = bm1[i];
    for (int i = threadIdx.x; i < DMSG; i += blockDim.x) sm[OFF_BM2+i] = bm2[i];
    for (int i = threadIdx.x; i < HTEN; i += blockDim.x) {
        sm[OFF_BT1+i] = bt1[i];
        sm[OFF_WT2+i] = Wt2[i];
    }
    if (threadIdx.x == 0) sm[OFF_BT2] = bt2[0];
    __syncthreads();

    const int lane = threadIdx.x & 31;
    const int warp = threadIdx.x >> 5;
    const int half = lane >> 4;
    const int l16  = lane & 15;
    const int l8   = lane & 7;

    float* ea_w = sm + OFF_EA + warp * (EK_B * 2 * DEDGE);
    float* ms_w = sm + OFF_MS + warp * (EK_B * 2 * DMSG);
    float* h_w  = sm + OFF_H  + warp * (EK_B * 2 * HCHUNK);

    const float4 b1p  = *(const float4*)(sm + OFF_BM1 + 4*lane);
    const float4 b2p  = *(const float4*)(sm + OFF_BM2 + 4*l16);
    const float2 bt1p = *(const float2*)(sm + OFF_BT1 + 2*l16);
    const float2 wt2p = *(const float2*)(sm + OFF_WT2 + 2*l16);
    const float  bt2v = sm[OFF_BT2];
    const ull    NEG1 = dup2(-1.0f);

    const bool idx64 = (g_idx64 != 0);
    const long long* ei64 = (const long long*)ei;
    const int*       ei32 = (const int*)ei;

    const int gw     = blockIdx.x * EK_NW + warp;
    const int nwarps = gridDim.x * EK_NW;

    for (int base = gw * EK_B; base < NE; base += nwarps * EK_B) {
        int sr[EK_B], tg[EK_B];
        #pragma unroll
        for (int e = 0; e < EK_B; e++) {
            int id = base + e;
            if (idx64) { sr[e] = (int)ei64[id]; tg[e] = (int)ei64[NE + id]; }
            else       { sr[e] = ei32[id];      tg[e] = ei32[NE + id]; }
        }

        // ---- stage duplicated edge attrs ----
        {
            int e = lane >> 2, l4 = lane & 3;
            float2 ev = *(const float2*)(ea + (size_t)(base + e)*DEDGE + 2*l4);
            float4 d; d.x = ev.x; d.y = ev.x; d.z = ev.y; d.w = ev.y;
            *(float4*)(ea_w + e*(2*DEDGE) + 4*l4) = d;
        }
        __syncwarp();

        // ---- layer 1 via precomputed y: z = y[t] - y[s] + Wm1[64:72]^T ea ----
        ull z[EK_B][2];
        #pragma unroll
        for (int e = 0; e < EK_B; e++) {
            ulonglong2 yt = *(const ulonglong2*)(g_y + (size_t)tg[e]*HMSG + 4*lane);
            ulonglong2 ys = *(const ulonglong2*)(g_y + (size_t)sr[e]*HMSG + 4*lane);
            z[e][0] = fma2(ys.x, NEG1, yt.x);
            z[e][1] = fma2(ys.y, NEG1, yt.y);
        }
        #pragma unroll
        for (int i = 0; i < DEDGE; i++) {
            ulonglong2 w2 = *(const ulonglong2*)(sm + OFF_WM1 + (DNODE+i)*HMSG + 4*lane);
            #pragma unroll
            for (int e = 0; e < EK_B; e++) {
                ull vv = *(const ull*)(ea_w + e*(2*DEDGE) + 2*i);
                z[e][0] = fma2(vv, w2.x, z[e][0]);
                z[e][1] = fma2(vv, w2.y, z[e][1]);
            }
        }

        // ---- layer 2 in four 32-j chunks; chunk c written by lanes 8c..8c+7 ----
        ull acc[4][4];
        #pragma unroll
        for (int es = 0; es < 4; es++)
            #pragma unroll
            for (int k = 0; k < 4; k++) acc[es][k] = 0ULL;

        const float* hp0 = h_w + (0 + half)*(2*HCHUNK);
        const float* hp1 = h_w + (2 + half)*(2*HCHUNK);
        const float* hp2 = h_w + (4 + half)*(2*HCHUNK);
        const float* hp3 = h_w + (6 + half)*(2*HCHUNK);

        #pragma unroll
        for (int c = 0; c < NCHUNK; c++) {
            if ((lane >> 3) == c) {
                #pragma unroll
                for (int e = 0; e < EK_B; e++) {
                    float2 za = unpack2(z[e][0]);
                    float2 zb = unpack2(z[e][1]);
                    float4 h0, h1;
                    h0.x = fmaxf(za.x + b1p.x, 0.f); h0.y = fmaxf(b1p.x - za.x, 0.f);
                    h0.z = fmaxf(za.y + b1p.y, 0.f); h0.w = fmaxf(b1p.y - za.y, 0.f);
                    h1.x = fmaxf(zb.x + b1p.z, 0.f); h1.y = fmaxf(b1p.z - zb.x, 0.f);
                    h1.z = fmaxf(zb.y + b1p.w, 0.f); h1.w = fmaxf(b1p.w - zb.y, 0.f);
                    *(float4*)(h_w + e*(2*HCHUNK) + 8*l8)     = h0; // j pair {f,b}
                    *(float4*)(h_w + e*(2*HCHUNK) + 8*l8 + 4) = h1;
                }
            }
            __syncwarp();

            #pragma unroll 2
            for (int jj = 0; jj < HCHUNK; jj += 2) {
                const int j0 = c*HCHUNK + jj;
                const float* wr0 = sm + OFF_W2D + j0*128 + 8*l16;
                const float* wr1 = wr0 + 128;
                ulonglong2 wA0 = *(const ulonglong2*)wr0;        // dup'd outs 0,1
                ulonglong2 wA1 = *(const ulonglong2*)(wr0 + 4);  // dup'd outs 2,3
                ulonglong2 wB0 = *(const ulonglong2*)wr1;
                ulonglong2 wB1 = *(const ulonglong2*)(wr1 + 4);
                ulonglong2 hA = *(const ulonglong2*)(hp0 + 2*jj); // {f0,b0,f1,b1}
                ulonglong2 hB = *(const ulonglong2*)(hp1 + 2*jj);
                ulonglong2 hC = *(const ulonglong2*)(hp2 + 2*jj);
                ulonglong2 hD = *(const ulonglong2*)(hp3 + 2*jj);
                acc[0][0] = fma2(hA.x, wA0.x, acc[0][0]);
                acc[0][1] = fma2(hA.x, wA0.y, acc[0][1]);
                acc[0][2] = fma2(hA.x, wA1.x, acc[0][2]);
                acc[0][3] = fma2(hA.x, wA1.y, acc[0][3]);
                acc[1][0] = fma2(hB.x, wA0.x, acc[1][0]);
                acc[1][1] = fma2(hB.x, wA0.y, acc[1][1]);
                acc[1][2] = fma2(hB.x, wA1.x, acc[1][2]);
                acc[1][3] = fma2(hB.x, wA1.y, acc[1][3]);
                acc[2][0] = fma2(hC.x, wA0.x, acc[2][0]);
                acc[2][1] = fma2(hC.x, wA0.y, acc[2][1]);
                acc[2][2] = fma2(hC.x, wA1.x, acc[2][2]);
                acc[2][3] = fma2(hC.x, wA1.y, acc[2][3]);
                acc[3][0] = fma2(hD.x, wA0.x, acc[3][0]);
                acc[3][1] = fma2(hD.x, wA0.y, acc[3][1]);
                acc[3][2] = fma2(hD.x, wA1.x, acc[3][2]);
                acc[3][3] = fma2(hD.x, wA1.y, acc[3][3]);
                acc[0][0] = fma2(hA.y, wB0.x, acc[0][0]);
                acc[0][1] = fma2(hA.y, wB0.y, acc[0][1]);
                acc[0][2] = fma2(hA.y, wB1.x, acc[0][2]);
                acc[0][3] = fma2(hA.y, wB1.y, acc[0][3]);
                acc[1][0] = fma2(hB.y, wB0.x, acc[1][0]);
                acc[1][1] = fma2(hB.y, wB0.y, acc[1][1]);
                acc[1][2] = fma2(hB.y, wB1.x, acc[1][2]);
                acc[1][3] = fma2(hB.y, wB1.y, acc[1][3]);
                acc[2][0] = fma2(hC.y, wB0.x, acc[2][0]);
                acc[2][1] = fma2(hC.y, wB0.y, acc[2][1]);
                acc[2][2] = fma2(hC.y, wB1.x, acc[2][2]);
                acc[2][3] = fma2(hC.y, wB1.y, acc[2][3]);
                acc[3][0] = fma2(hD.y, wB0.x, acc[3][0]);
                acc[3][1] = fma2(hD.y, wB0.y, acc[3][1]);
                acc[3][2] = fma2(hD.y, wB1.x, acc[3][2]);
                acc[3][3] = fma2(hD.y, wB1.y, acc[3][3]);
            }
            __syncwarp();
        }

        // ---- bias+relu, RED scatter, m_sym (dup'd) ----
        #pragma unroll
        for (int es = 0; es < 4; es++) {
            const int e = 2*es + half;
            const int t = half ? tg[2*es+1] : tg[2*es];
            const int s = half ? sr[2*es+1] : sr[2*es];
            float2 a0 = unpack2(acc[es][0]);
            float2 a1 = unpack2(acc[es][1]);
            float2 a2 = unpack2(acc[es][2]);
            float2 a3 = unpack2(acc[es][3]);
            float f0 = fmaxf(a0.x + b2p.x, 0.f), g0 = fmaxf(a0.y + b2p.x, 0.f);
            float f1 = fmaxf(a1.x + b2p.y, 0.f), g1 = fmaxf(a1.y + b2p.y, 0.f);
            float f2 = fmaxf(a2.x + b2p.z, 0.f), g2 = fmaxf(a2.y + b2p.z, 0.f);
            float f3 = fmaxf(a3.x + b2p.w, 0.f), g3 = fmaxf(a3.y + b2p.w, 0.f);
            red_add_v2(g_aggr + (size_t)t*DMSG + 4*l16,     f0, f1);
            red_add_v2(g_aggr + (size_t)t*DMSG + 4*l16 + 2, f2, f3);
            red_add_v2(g_aggr + (size_t)s*DMSG + 4*l16,     g0, g1);
            red_add_v2(g_aggr + (size_t)s*DMSG + 4*l16 + 2, g2, g3);
            float s0 = f0+g0, s1 = f1+g1, s2 = f2+g2, s3 = f3+g3;
            float4 svA; svA.x = s0; svA.y = s0; svA.z = s1; svA.w = s1;
            float4 svB; svB.x = s2; svB.y = s2; svB.z = s3; svB.w = s3;
            *(float4*)(ms_w + e*(2*DMSG) + 8*l16)     = svA;
            *(float4*)(ms_w + e*(2*DMSG) + 8*l16 + 4) = svB;
        }
        if (lane < 2*EK_B) {
            int e = lane >> 1;
            int node = (lane & 1) ? sr[e] : tg[e];
            red_add_f32(g_cnt + node, 1.f);
        }
        __syncwarp();

        // ---- tension MLP: paired-transposed Wt1, all edges in one d-loop ----
        ull tac[4];
        tac[0] = 0ULL; tac[1] = 0ULL; tac[2] = 0ULL; tac[3] = 0ULL;
        #pragma unroll 4
        for (int s = 0; s < 32; s++) {
            ulonglong2 w = *(const ulonglong2*)(sm + OFF_WT1 + s*64 + 4*l16);
            #pragma unroll
            for (int p = 0; p < 4; p++) {
                const float* msp = ms_w + (2*p + half)*(2*DMSG);
                ulonglong2 mv = *(const ulonglong2*)(msp + 4*s);
                tac[p] = fma2(mv.x, w.x, tac[p]);
                tac[p] = fma2(mv.y, w.y, tac[p]);
            }
        }
        #pragma unroll
        for (int p = 0; p < 4; p++) {
            float2 ac = unpack2(tac[p]);
            float h0 = fmaxf(ac.x + bt1p.x, 0.f);
            float h1 = fmaxf(ac.y + bt1p.y, 0.f);
            float c  = h0*wt2p.x + h1*wt2p.y;
            #pragma unroll
            for (int off = 8; off > 0; off >>= 1)
                c += __shfl_xor_sync(0xffffffffu, c, off);
            if (l16 == 0) e_out[base + 2*p + half] = c + bt2v;
        }
        __syncwarp();
    }
}

// ---------------- node kernel v2 (unchanged from R14) ----------------
#define NK_NW 16
#define NB    4
#define NOFF_W1T 0
#define NOFF_W2T (NOFF_W1T + 8192)
#define NOFF_BU1 (NOFF_W2T + 2048)
#define NOFF_BU2 (NOFF_BU1 + HUPD)
#define NOFF_IN  (NOFF_BU2 + DOUT)
#define NOFF_H   (NOFF_IN + NK_NW*NB*(DNODE+DMSG))
#define NK_SMEM_FLOATS (NOFF_H + NK_NW*NB*HUPD)

__global__ void __launch_bounds__(NK_NW * 32, 1)
node_kernel(const float* __restrict__ x,
            const float* __restrict__ Wu1, const float* __restrict__ bu1,
            const float* __restrict__ Wu2, const float* __restrict__ bu2,
            float* __restrict__ x_out)
{
    extern __shared__ float sm[];
    for (int idx = threadIdx.x; idx < 64*64; idx += blockDim.x) {
        int s = idx >> 6, k = idx & 63;
        sm[NOFF_W1T + s*128 + 2*k]     = Wu1[(2*s)*HUPD   + k];
        sm[NOFF_W1T + s*128 + 2*k + 1] = Wu1[(2*s+1)*HUPD + k];
    }
    for (int idx = threadIdx.x; idx < 32*32; idx += blockDim.x) {
        int s = idx >> 5, o = idx & 31;
        sm[NOFF_W2T + s*64 + 2*o]     = Wu2[(2*s)*DOUT   + o];
        sm[NOFF_W2T + s*64 + 2*o + 1] = Wu2[(2*s+1)*DOUT + o];
    }
    for (int i = threadIdx.x; i < HUPD; i += blockDim.x) sm[NOFF_BU1+i] = bu1[i];
    for (int i = threadIdx.x; i < DOUT; i += blockDim.x) sm[NOFF_BU2+i] = bu2[i];
    __syncthreads();

    const int lane = threadIdx.x & 31;
    const int warp = threadIdx.x >> 5;
    float* in_w = sm + NOFF_IN + warp * (NB * 128);
    float* h_w  = sm + NOFF_H  + warp * (NB * HUPD);

    const float2 b1 = *(const float2*)(sm + NOFF_BU1 + 2*lane);
    const float  b2 = sm[NOFF_BU2 + lane];

    const int gw     = blockIdx.x * NK_NW + warp;
    const int nwarps = gridDim.x * NK_NW;

    for (int n0 = gw * NB; n0 < NN; n0 += nwarps * NB) {
        #pragma unroll
        for (int e = 0; e < NB; e++) {
            int n = n0 + e; if (n >= NN) n = NN - 1;
            float inv = 1.f / fmaxf(g_cnt[n], 1.f);
            float2 xv = *(const float2*)(x + (size_t)n*DNODE + 2*lane);
            float2 av = *(const float2*)(g_aggr + (size_t)n*DMSG + 2*lane);
            av.x *= inv; av.y *= inv;
            *(float2*)(in_w + e*128 + 2*lane)      = xv;
            *(float2*)(in_w + e*128 + 64 + 2*lane) = av;
        }
        __syncwarp();

        ull accA[NB], accB[NB];
        #pragma unroll
        for (int e = 0; e < NB; e++) { accA[e] = 0ULL; accB[e] = 0ULL; }

        #pragma unroll 8
        for (int s = 0; s < 64; s++) {
            ulonglong2 w = *(const ulonglong2*)(sm + NOFF_W1T + s*128 + 4*lane);
            #pragma unroll
            for (int e = 0; e < NB; e++) {
                ull vv = *(const ull*)(in_w + e*128 + 2*s);
                accA[e] = fma2(vv, w.x, accA[e]);
                accB[e] = fma2(vv, w.y, accB[e]);
            }
        }
        #pragma unroll
        for (int e = 0; e < NB; e++) {
            float2 a = unpack2(accA[e]);
            float2 b = unpack2(accB[e]);
            float2 h;
            h.x = fmaxf(a.x + a.y + b1.x, 0.f);
            h.y = fmaxf(b.x + b.y + b1.y, 0.f);
            *(float2*)(h_w + e*HUPD + 2*lane) = h;
        }
        __syncwarp();

        ull acc2[NB];
        #pragma unroll
        for (int e = 0; e < NB; e++) acc2[e] = 0ULL;
        #pragma unroll 8
        for (int s = 0; s < 32; s++) {
            ull w = *(const ull*)(sm + NOFF_W2T + s*64 + 2*lane);
            #pragma unroll
            for (int e = 0; e < NB; e++) {
                ull hv = *(const ull*)(h_w + e*HUPD + 2*s);
                acc2[e] = fma2(hv, w, acc2[e]);
            }
        }
        #pragma unroll
        for (int e = 0; e < NB; e++) {
            int n = n0 + e;
            if (n < NN) {
                float2 a = unpack2(acc2[e]);
                x_out[(size_t)n*DOUT + lane] = a.x + a.y + b2;
            }
        }
        __syncwarp();
    }
}

// ---------------- launch ----------------
extern "C" void kernel_launch(void* const* d_in, const int* in_sizes, int n_in,
                              void* d_out, int out_size)
{
    (void)in_sizes; (void)n_in; (void)out_size;
    const float* x   = (const float*)d_in[0];
    const void*  ei  =               d_in[1];
    const float* ea  = (const float*)d_in[2];
    const float* Wm1 = (const float*)d_in[3];
    const float* bm1 = (const float*)d_in[4];
    const float* Wm2 = (const float*)d_in[5];
    const float* bm2 = (const float*)d_in[6];
    const float* Wu1 = (const float*)d_in[7];
    const float* bu1 = (const float*)d_in[8];
    const float* Wu2 = (const float*)d_in[9];
    const float* bu2 = (const float*)d_in[10];
    const float* Wt1 = (const float*)d_in[11];
    const float* bt1 = (const float*)d_in[12];
    const float* Wt2 = (const float*)d_in[13];
    const float* bt2 = (const float*)d_in[14];

    float* x_out = (float*)d_out;
    float* e_out = x_out + (size_t)NN * DOUT;

    int nsm = 148;
    cudaDeviceGetAttribute(&nsm, cudaDevAttrMultiProcessorCount, 0);

    cudaFuncSetAttribute(precompute_y_kernel, cudaFuncAttributeMaxDynamicSharedMemorySize,
                         PY_SMEM_FLOATS * (int)sizeof(float));
    cudaFuncSetAttribute(edge_kernel, cudaFuncAttributeMaxDynamicSharedMemorySize,
                         EK_SMEM_FLOATS * (int)sizeof(float));
    cudaFuncSetAttribute(node_kernel, cudaFuncAttributeMaxDynamicSharedMemorySize,
                         NK_SMEM_FLOATS * (int)sizeof(float));

    init_kernel<<<1024, 256>>>(ei);
    precompute_y_kernel<<<nsm, PY_NW * 32, PY_SMEM_FLOATS * sizeof(float)>>>(x, Wm1);
    edge_kernel<<<nsm, EK_NW * 32, EK_SMEM_FLOATS * sizeof(float)>>>(
        ei, ea, Wm1, bm1, Wm2, bm2, Wt1, bt1, Wt2, bt2, e_out);
    node_kernel<<<2*nsm, NK_NW * 32, NK_SMEM_FLOATS * sizeof(float)>>>(
        x, Wu1, bu1, Wu2, bu2, x_out);
}

// round 17
// speedup vs baseline: 1.8061x; 1.5473x over previous
#include <cuda_runtime.h>
#include <cstdint>
#include <cstddef>

// ---------------- problem constants ----------------
#define NN     50000
#define NE     500000
#define DNODE  64
#define DEDGE  8
#define DIN    72
#define HMSG   128
#define DMSG   64
#define HUPD   64
#define DOUT   32
#define HTEN   32

typedef unsigned long long ull;

// ---------------- device scratch ----------------
__device__ float g_aggr[(size_t)NN * DMSG];
__device__ float g_cnt[NN];
__device__ float g_y[(size_t)NN * HMSG];     // y = x @ Wm1[0:64]  (25.6 MB)
__device__ int   g_idx64;

// ---------------- packed f32x2 helpers ----------------
__device__ __forceinline__ ull fma2(ull a, ull b, ull c) {
    ull d; asm("fma.rn.f32x2 %0, %1, %2, %3;" : "=l"(d) : "l"(a), "l"(b), "l"(c));
    return d;
}
__device__ __forceinline__ ull dup2(float x) {
    ull d; asm("mov.b64 %0, {%1, %1};" : "=l"(d) : "f"(x)); return d;
}
__device__ __forceinline__ float2 unpack2(ull v) {
    float2 r; asm("mov.b64 {%0, %1}, %2;" : "=f"(r.x), "=f"(r.y) : "l"(v)); return r;
}
__device__ __forceinline__ void red_add_v2(float* addr, float a, float b) {
    asm volatile("red.global.add.v2.f32 [%0], {%1, %2};"
                 :: "l"(addr), "f"(a), "f"(b) : "memory");
}
__device__ __forceinline__ void red_add_f32(float* addr, float v) {
    asm volatile("red.global.add.f32 [%0], %1;"
                 :: "l"(addr), "f"(v) : "memory");
}

// ---------------- precompute y = x @ Wm1[0:64,:]  (+ init folded in) -------
#define PY_NW 16
#define PYOFF_W 0
#define PYOFF_X (PYOFF_W + DNODE*HMSG)
#define PY_SMEM_FLOATS (PYOFF_X + PY_NW*2*DNODE)

__global__ void __launch_bounds__(PY_NW * 32, 1)
precompute_y_kernel(const float* __restrict__ x, const float* __restrict__ Wm1,
                    const void* __restrict__ ei)
{
    // ---- folded init: zero scratch + detect index dtype ----
    {
        size_t tid    = (size_t)blockIdx.x * blockDim.x + threadIdx.x;
        size_t stride = (size_t)gridDim.x * blockDim.x;
        for (size_t i = tid; i < (size_t)NN * DMSG; i += stride) g_aggr[i] = 0.f;
        for (size_t i = tid; i < (size_t)NN; i += stride)        g_cnt[i]  = 0.f;
        if (blockIdx.x == 0 && threadIdx.x == 0) {
            const unsigned long long* p = (const unsigned long long*)ei;
            int is64 = 1;
            for (int k = 0; k < 64; k++)
                if (p[k] >= (unsigned long long)NN) { is64 = 0; break; }
            g_idx64 = is64;
        }
    }

    extern __shared__ float sm[];
    for (int i = threadIdx.x; i < DNODE*HMSG; i += blockDim.x) sm[PYOFF_W+i] = Wm1[i];
    __syncthreads();

    const int lane = threadIdx.x & 31;
    const int warp = threadIdx.x >> 5;
    float* xs_w = sm + PYOFF_X + warp * (2*DNODE);

    const int gw     = blockIdx.x * PY_NW + warp;
    const int nwarps = gridDim.x * PY_NW;

    for (int n = gw; n < NN; n += nwarps) {
        const float2 xv = *(const float2*)(x + (size_t)n*DNODE + 2*lane);
        float4 d; d.x = xv.x; d.y = xv.x; d.z = xv.y; d.w = xv.y;
        *(float4*)(xs_w + 4*lane) = d;
        __syncwarp();

        ull a0 = 0ULL, a1 = 0ULL;
        #pragma unroll 8
        for (int i = 0; i < DNODE; i++) {
            ulonglong2 w2 = *(const ulonglong2*)(sm + PYOFF_W + i*HMSG + 4*lane);
            ull vv = *(const ull*)(xs_w + 2*i);
            a0 = fma2(vv, w2.x, a0);
            a1 = fma2(vv, w2.y, a1);
        }
        ulonglong2 o; o.x = a0; o.y = a1;
        *(ulonglong2*)(g_y + (size_t)n*HMSG + 4*lane) = o;
        __syncwarp();
    }
}

// ---------------- edge kernel: EXACT R14 (measured 542.8us) ----------------
#define EK_NW 16
#define EK_B  8
#define HCHUNK 64

#define OFF_WM1 0
#define OFF_WM2 (OFF_WM1 + DIN*HMSG)            // 9216
#define OFF_WT1 (OFF_WM2 + HMSG*DMSG)           // 17408 (d-pair transposed)
#define OFF_BM1 (OFF_WT1 + DMSG*HTEN)           // 19456
#define OFF_BM2 (OFF_BM1 + HMSG)                // 19584
#define OFF_BT1 (OFF_BM2 + DMSG)                // 19648
#define OFF_WT2 (OFF_BT1 + HTEN)                // 19680
#define OFF_BT2 (OFF_WT2 + HTEN)                // 19712
#define OFF_EA  (OFF_BT2 + 4)                   // 19716 (16B aligned)
#define OFF_MS  (OFF_EA + EK_NW*EK_B*2*DEDGE)   // +16*128  = 21764
#define OFF_H   (OFF_MS + EK_NW*EK_B*2*DMSG)    // +16*1024 = 38148
#define EK_SMEM_FLOATS (OFF_H + EK_NW*EK_B*2*HCHUNK) // +16*1024 = 54532 fl (218KB)

__global__ void __launch_bounds__(EK_NW * 32, 1)
edge_kernel(const void* __restrict__ ei,
            const float* __restrict__ ea,
            const float* __restrict__ Wm1, const float* __restrict__ bm1,
            const float* __restrict__ Wm2, const float* __restrict__ bm2,
            const float* __restrict__ Wt1, const float* __restrict__ bt1,
            const float* __restrict__ Wt2, const float* __restrict__ bt2,
            float* __restrict__ e_out)
{
    extern __shared__ float sm[];
    for (int i = threadIdx.x; i < DIN*HMSG;  i += blockDim.x) sm[OFF_WM1+i] = Wm1[i];
    for (int i = threadIdx.x; i < HMSG*DMSG; i += blockDim.x) sm[OFF_WM2+i] = Wm2[i];
    // Wt1 d-pair transposed
    for (int idx = threadIdx.x; idx < 32*16; idx += blockDim.x) {
        int s = idx >> 4, k = idx & 15;
        float* dst = sm + OFF_WT1 + s*64 + 4*k;
        dst[0] = Wt1[(2*s)*HTEN   + 2*k];
        dst[1] = Wt1[(2*s)*HTEN   + 2*k+1];
        dst[2] = Wt1[(2*s+1)*HTEN + 2*k];
        dst[3] = Wt1[(2*s+1)*HTEN + 2*k+1];
    }
    for (int i = threadIdx.x; i < HMSG; i += blockDim.x) sm[OFF_BM1+i] = bm1[i];
    for (int i = threadIdx.x; i < DMSG; i += blockDim.x) sm[OFF_BM2+i] = bm2[i];
    for (int i = threadIdx.x; i < HTEN; i += blockDim.x) {
        sm[OFF_BT1+i] = bt1[i];
        sm[OFF_WT2+i] = Wt2[i];
    }
    if (threadIdx.x == 0) sm[OFF_BT2] = bt2[0];
    __syncthreads();

    const int lane = threadIdx.x & 31;
    const int warp = threadIdx.x >> 5;
    const int half = lane >> 4;
    const int l16  = lane & 15;

    float* ea_w = sm + OFF_EA + warp * (EK_B * 2 * DEDGE);
    float* ms_w = sm + OFF_MS + warp * (EK_B * 2 * DMSG);
    float* h_w  = sm + OFF_H  + warp * (EK_B * 2 * HCHUNK);

    const float4 b1p  = *(const float4*)(sm + OFF_BM1 + 4*lane);
    const float4 b2p  = *(const float4*)(sm + OFF_BM2 + 4*l16);
    const float2 bt1p = *(const float2*)(sm + OFF_BT1 + 2*l16);
    const float2 wt2p = *(const float2*)(sm + OFF_WT2 + 2*l16);
    const float  bt2v = sm[OFF_BT2];
    const ull    NEG1 = dup2(-1.0f);

    const bool idx64 = (g_idx64 != 0);
    const long long* ei64 = (const long long*)ei;
    const int*       ei32 = (const int*)ei;

    const int gw     = blockIdx.x * EK_NW + warp;
    const int nwarps = gridDim.x * EK_NW;

    for (int base = gw * EK_B; base < NE; base += nwarps * EK_B) {
        int sr[EK_B], tg[EK_B];
        #pragma unroll
        for (int e = 0; e < EK_B; e++) {
            int id = base + e;
            if (idx64) { sr[e] = (int)ei64[id]; tg[e] = (int)ei64[NE + id]; }
            else       { sr[e] = ei32[id];      tg[e] = ei32[NE + id]; }
        }

        // ---- stage duplicated edge attrs ----
        {
            int e = lane >> 2, l4 = lane & 3;
            float2 ev = *(const float2*)(ea + (size_t)(base + e)*DEDGE + 2*l4);
            float4 d; d.x = ev.x; d.y = ev.x; d.z = ev.y; d.w = ev.y;
            *(float4*)(ea_w + e*(2*DEDGE) + 4*l4) = d;
        }
        __syncwarp();

        // ---- layer 1 via precomputed y: z = y[t] - y[s] + Wm1[64:72]^T ea ----
        ull z[EK_B][2];
        #pragma unroll
        for (int e = 0; e < EK_B; e++) {
            ulonglong2 yt = *(const ulonglong2*)(g_y + (size_t)tg[e]*HMSG + 4*lane);
            ulonglong2 ys = *(const ulonglong2*)(g_y + (size_t)sr[e]*HMSG + 4*lane);
            z[e][0] = fma2(ys.x, NEG1, yt.x);
            z[e][1] = fma2(ys.y, NEG1, yt.y);
        }
        #pragma unroll
        for (int i = 0; i < DEDGE; i++) {
            ulonglong2 w2 = *(const ulonglong2*)(sm + OFF_WM1 + (DNODE+i)*HMSG + 4*lane);
            #pragma unroll
            for (int e = 0; e < EK_B; e++) {
                ull vv = *(const ull*)(ea_w + e*(2*DEDGE) + 2*i);
                z[e][0] = fma2(vv, w2.x, z[e][0]);
                z[e][1] = fma2(vv, w2.y, z[e][1]);
            }
        }

        // ---- layer 2 in two 64-j chunks sharing one small h buffer ----
        ull acc[4][4];
        #pragma unroll
        for (int es = 0; es < 4; es++)
            #pragma unroll
            for (int k = 0; k < 4; k++) acc[es][k] = 0ULL;

        const float* hp0 = h_w + (0 + half)*(2*HCHUNK);
        const float* hp1 = h_w + (2 + half)*(2*HCHUNK);
        const float* hp2 = h_w + (4 + half)*(2*HCHUNK);
        const float* hp3 = h_w + (6 + half)*(2*HCHUNK);

        #pragma unroll
        for (int c = 0; c < 2; c++) {
            if (half == c) {
                #pragma unroll
                for (int e = 0; e < EK_B; e++) {
                    float2 za = unpack2(z[e][0]);
                    float2 zb = unpack2(z[e][1]);
                    float4 h0, h1;
                    h0.x = fmaxf(za.x + b1p.x, 0.f); h0.y = fmaxf(b1p.x - za.x, 0.f);
                    h0.z = fmaxf(za.y + b1p.y, 0.f); h0.w = fmaxf(b1p.y - za.y, 0.f);
                    h1.x = fmaxf(zb.x + b1p.z, 0.f); h1.y = fmaxf(b1p.z - zb.x, 0.f);
                    h1.z = fmaxf(zb.y + b1p.w, 0.f); h1.w = fmaxf(b1p.w - zb.y, 0.f);
                    *(float4*)(h_w + e*(2*HCHUNK) + 8*l16)     = h0; // {f,b} j pair
                    *(float4*)(h_w + e*(2*HCHUNK) + 8*l16 + 4) = h1;
                }
            }
            __syncwarp();

            #pragma unroll 2
            for (int jj = 0; jj < HCHUNK; jj += 2) {
                const float* wrow = sm + OFF_WM2 + (c*HCHUNK + jj)*DMSG + 4*l16;
                ulonglong2 wj0 = *(const ulonglong2*)wrow;
                ulonglong2 wj1 = *(const ulonglong2*)(wrow + DMSG);
                float2 w0lo = unpack2(wj0.x), w0hi = unpack2(wj0.y);
                float2 w1lo = unpack2(wj1.x), w1hi = unpack2(wj1.y);
                ull a0 = dup2(w0lo.x), a1 = dup2(w0lo.y), a2 = dup2(w0hi.x), a3 = dup2(w0hi.y);
                ull b0 = dup2(w1lo.x), b1 = dup2(w1lo.y), b2 = dup2(w1hi.x), b3 = dup2(w1hi.y);
                ulonglong2 hA = *(const ulonglong2*)(hp0 + 2*jj);
                ulonglong2 hB = *(const ulonglong2*)(hp1 + 2*jj);
                ulonglong2 hC = *(const ulonglong2*)(hp2 + 2*jj);
                ulonglong2 hD = *(const ulonglong2*)(hp3 + 2*jj);
                acc[0][0] = fma2(hA.x, a0, acc[0][0]);
                acc[0][1] = fma2(hA.x, a1, acc[0][1]);
                acc[0][2] = fma2(hA.x, a2, acc[0][2]);
                acc[0][3] = fma2(hA.x, a3, acc[0][3]);
                acc[1][0] = fma2(hB.x, a0, acc[1][0]);
                acc[1][1] = fma2(hB.x, a1, acc[1][1]);
                acc[1][2] = fma2(hB.x, a2, acc[1][2]);
                acc[1][3] = fma2(hB.x, a3, acc[1][3]);
                acc[2][0] = fma2(hC.x, a0, acc[2][0]);
                acc[2][1] = fma2(hC.x, a1, acc[2][1]);
                acc[2][2] = fma2(hC.x, a2, acc[2][2]);
                acc[2][3] = fma2(hC.x, a3, acc[2][3]);
                acc[3][0] = fma2(hD.x, a0, acc[3][0]);
                acc[3][1] = fma2(hD.x, a1, acc[3][1]);
                acc[3][2] = fma2(hD.x, a2, acc[3][2]);
                acc[3][3] = fma2(hD.x, a3, acc[3][3]);
                acc[0][0] = fma2(hA.y, b0, acc[0][0]);
                acc[0][1] = fma2(hA.y, b1, acc[0][1]);
                acc[0][2] = fma2(hA.y, b2, acc[0][2]);
                acc[0][3] = fma2(hA.y, b3, acc[0][3]);
                acc[1][0] = fma2(hB.y, b0, acc[1][0]);
                acc[1][1] = fma2(hB.y, b1, acc[1][1]);
                acc[1][2] = fma2(hB.y, b2, acc[1][2]);
                acc[1][3] = fma2(hB.y, b3, acc[1][3]);
                acc[2][0] = fma2(hC.y, b0, acc[2][0]);
                acc[2][1] = fma2(hC.y, b1, acc[2][1]);
                acc[2][2] = fma2(hC.y, b2, acc[2][2]);
                acc[2][3] = fma2(hC.y, b3, acc[2][3]);
                acc[3][0] = fma2(hD.y, b0, acc[3][0]);
                acc[3][1] = fma2(hD.y, b1, acc[3][1]);
                acc[3][2] = fma2(hD.y, b2, acc[3][2]);
                acc[3][3] = fma2(hD.y, b3, acc[3][3]);
            }
            __syncwarp();
        }

        // ---- bias+relu, RED scatter, m_sym (dup'd) ----
        #pragma unroll
        for (int es = 0; es < 4; es++) {
            const int e = 2*es + half;
            const int t = half ? tg[2*es+1] : tg[2*es];
            const int s = half ? sr[2*es+1] : sr[2*es];
            float2 a0 = unpack2(acc[es][0]);
            float2 a1 = unpack2(acc[es][1]);
            float2 a2 = unpack2(acc[es][2]);
            float2 a3 = unpack2(acc[es][3]);
            float f0 = fmaxf(a0.x + b2p.x, 0.f), g0 = fmaxf(a0.y + b2p.x, 0.f);
            float f1 = fmaxf(a1.x + b2p.y, 0.f), g1 = fmaxf(a1.y + b2p.y, 0.f);
            float f2 = fmaxf(a2.x + b2p.z, 0.f), g2 = fmaxf(a2.y + b2p.z, 0.f);
            float f3 = fmaxf(a3.x + b2p.w, 0.f), g3 = fmaxf(a3.y + b2p.w, 0.f);
            red_add_v2(g_aggr + (size_t)t*DMSG + 4*l16,     f0, f1);
            red_add_v2(g_aggr + (size_t)t*DMSG + 4*l16 + 2, f2, f3);
            red_add_v2(g_aggr + (size_t)s*DMSG + 4*l16,     g0, g1);
            red_add_v2(g_aggr + (size_t)s*DMSG + 4*l16 + 2, g2, g3);
            float s0 = f0+g0, s1 = f1+g1, s2 = f2+g2, s3 = f3+g3;
            float4 svA; svA.x = s0; svA.y = s0; svA.z = s1; svA.w = s1;
            float4 svB; svB.x = s2; svB.y = s2; svB.z = s3; svB.w = s3;
            *(float4*)(ms_w + e*(2*DMSG) + 8*l16)     = svA;
            *(float4*)(ms_w + e*(2*DMSG) + 8*l16 + 4) = svB;
        }
        if (lane < 2*EK_B) {
            int e = lane >> 1;
            int node = (lane & 1) ? sr[e] : tg[e];
            red_add_f32(g_cnt + node, 1.f);
        }
        __syncwarp();

        // ---- tension MLP: paired-transposed Wt1, all edges in one d-loop ----
        ull tac[4];
        tac[0] = 0ULL; tac[1] = 0ULL; tac[2] = 0ULL; tac[3] = 0ULL;
        #pragma unroll 4
        for (int s = 0; s < 32; s++) {
            ulonglong2 w = *(const ulonglong2*)(sm + OFF_WT1 + s*64 + 4*l16);
            #pragma unroll
            for (int p = 0; p < 4; p++) {
                const float* msp = ms_w + (2*p + half)*(2*DMSG);
                ulonglong2 mv = *(const ulonglong2*)(msp + 4*s);
                tac[p] = fma2(mv.x, w.x, tac[p]);
                tac[p] = fma2(mv.y, w.y, tac[p]);
            }
        }
        #pragma unroll
        for (int p = 0; p < 4; p++) {
            float2 ac = unpack2(tac[p]);
            float h0 = fmaxf(ac.x + bt1p.x, 0.f);
            float h1 = fmaxf(ac.y + bt1p.y, 0.f);
            float c  = h0*wt2p.x + h1*wt2p.y;
            #pragma unroll
            for (int off = 8; off > 0; off >>= 1)
                c += __shfl_xor_sync(0xffffffffu, c, off);
            if (l16 == 0) e_out[base + 2*p + half] = c + bt2v;
        }
        __syncwarp();
    }
}

// ---------------- node kernel: R14 + paired broadcast loads ----------------
#define NK_NW 16
#define NB    4
#define NOFF_W1T 0
#define NOFF_W2T (NOFF_W1T + 8192)
#define NOFF_BU1 (NOFF_W2T + 2048)
#define NOFF_BU2 (NOFF_BU1 + HUPD)
#define NOFF_IN  (NOFF_BU2 + DOUT)
#define NOFF_H   (NOFF_IN + NK_NW*NB*(DNODE+DMSG))
#define NK_SMEM_FLOATS (NOFF_H + NK_NW*NB*HUPD)

__global__ void __launch_bounds__(NK_NW * 32, 1)
node_kernel(const float* __restrict__ x,
            const float* __restrict__ Wu1, const float* __restrict__ bu1,
            const float* __restrict__ Wu2, const float* __restrict__ bu2,
            float* __restrict__ x_out)
{
    extern __shared__ float sm[];
    for (int idx = threadIdx.x; idx < 64*64; idx += blockDim.x) {
        int s = idx >> 6, k = idx & 63;
        sm[NOFF_W1T + s*128 + 2*k]     = Wu1[(2*s)*HUPD   + k];
        sm[NOFF_W1T + s*128 + 2*k + 1] = Wu1[(2*s+1)*HUPD + k];
    }
    for (int idx = threadIdx.x; idx < 32*32; idx += blockDim.x) {
        int s = idx >> 5, o = idx & 31;
        sm[NOFF_W2T + s*64 + 2*o]     = Wu2[(2*s)*DOUT   + o];
        sm[NOFF_W2T + s*64 + 2*o + 1] = Wu2[(2*s+1)*DOUT + o];
    }
    for (int i = threadIdx.x; i < HUPD; i += blockDim.x) sm[NOFF_BU1+i] = bu1[i];
    for (int i = threadIdx.x; i < DOUT; i += blockDim.x) sm[NOFF_BU2+i] = bu2[i];
    __syncthreads();

    const int lane = threadIdx.x & 31;
    const int warp = threadIdx.x >> 5;
    float* in_w = sm + NOFF_IN + warp * (NB * 128);
    float* h_w  = sm + NOFF_H  + warp * (NB * HUPD);

    const float2 b1 = *(const float2*)(sm + NOFF_BU1 + 2*lane);
    const float  b2 = sm[NOFF_BU2 + lane];

    const int gw     = blockIdx.x * NK_NW + warp;
    const int nwarps = gridDim.x * NK_NW;

    for (int n0 = gw * NB; n0 < NN; n0 += nwarps * NB) {
        #pragma unroll
        for (int e = 0; e < NB; e++) {
            int n = n0 + e; if (n >= NN) n = NN - 1;
            float inv = 1.f / fmaxf(g_cnt[n], 1.f);
            float2 xv = *(const float2*)(x + (size_t)n*DNODE + 2*lane);
            float2 av = *(const float2*)(g_aggr + (size_t)n*DMSG + 2*lane);
            av.x *= inv; av.y *= inv;
            *(float2*)(in_w + e*128 + 2*lane)      = xv;
            *(float2*)(in_w + e*128 + 64 + 2*lane) = av;
        }
        __syncwarp();

        // ---- layer 1: two s-steps per iteration (one ulonglong2 broadcast) ----
        ull accA[NB], accB[NB];
        #pragma unroll
        for (int e = 0; e < NB; e++) { accA[e] = 0ULL; accB[e] = 0ULL; }

        #pragma unroll 4
        for (int s = 0; s < 64; s += 2) {
            ulonglong2 wa = *(const ulonglong2*)(sm + NOFF_W1T + s*128     + 4*lane);
            ulonglong2 wb = *(const ulonglong2*)(sm + NOFF_W1T + (s+1)*128 + 4*lane);
            #pragma unroll
            for (int e = 0; e < NB; e++) {
                ulonglong2 vv = *(const ulonglong2*)(in_w + e*128 + 2*s); // {v2s..v2s+3}
                accA[e] = fma2(vv.x, wa.x, accA[e]);
                accB[e] = fma2(vv.x, wa.y, accB[e]);
                accA[e] = fma2(vv.y, wb.x, accA[e]);
                accB[e] = fma2(vv.y, wb.y, accB[e]);
            }
        }
        #pragma unroll
        for (int e = 0; e < NB; e++) {
            float2 a = unpack2(accA[e]);
            float2 b = unpack2(accB[e]);
            float2 h;
            h.x = fmaxf(a.x + a.y + b1.x, 0.f);
            h.y = fmaxf(b.x + b.y + b1.y, 0.f);
            *(float2*)(h_w + e*HUPD + 2*lane) = h;
        }
        __syncwarp();

        // ---- layer 2: two s-steps per iteration ----
        ull acc2[NB];
        #pragma unroll
        for (int e = 0; e < NB; e++) acc2[e] = 0ULL;
        #pragma unroll 4
        for (int s = 0; s < 32; s += 2) {
            ull w0 = *(const ull*)(sm + NOFF_W2T + s*64     + 2*lane);
            ull w1 = *(const ull*)(sm + NOFF_W2T + (s+1)*64 + 2*lane);
            #pragma unroll
            for (int e = 0; e < NB; e++) {
                ulonglong2 hv = *(const ulonglong2*)(h_w + e*HUPD + 2*s); // {h2s..h2s+3}
                acc2[e] = fma2(hv.x, w0, acc2[e]);
                acc2[e] = fma2(hv.y, w1, acc2[e]);
            }
        }
        #pragma unroll
        for (int e = 0; e < NB; e++) {
            int n = n0 + e;
            if (n < NN) {
                float2 a = unpack2(acc2[e]);
                x_out[(size_t)n*DOUT + lane] = a.x + a.y + b2;
            }
        }
        __syncwarp();
    }
}

// ---------------- launch ----------------
extern "C" void kernel_launch(void* const* d_in, const int* in_sizes, int n_in,
                              void* d_out, int out_size)
{
    (void)in_sizes; (void)n_in; (void)out_size;
    const float* x   = (const float*)d_in[0];
    const void*  ei  =               d_in[1];
    const float* ea  = (const float*)d_in[2];
    const float* Wm1 = (const float*)d_in[3];
    const float* bm1 = (const float*)d_in[4];
    const float* Wm2 = (const float*)d_in[5];
    const float* bm2 = (const float*)d_in[6];
    const float* Wu1 = (const float*)d_in[7];
    const float* bu1 = (const float*)d_in[8];
    const float* Wu2 = (const float*)d_in[9];
    const float* bu2 = (const float*)d_in[10];
    const float* Wt1 = (const float*)d_in[11];
    const float* bt1 = (const float*)d_in[12];
    const float* Wt2 = (const float*)d_in[13];
    const float* bt2 = (const float*)d_in[14];

    float* x_out = (float*)d_out;
    float* e_out = x_out + (size_t)NN * DOUT;

    int nsm = 148;
    cudaDeviceGetAttribute(&nsm, cudaDevAttrMultiProcessorCount, 0);

    cudaFuncSetAttribute(precompute_y_kernel, cudaFuncAttributeMaxDynamicSharedMemorySize,
                         PY_SMEM_FLOATS * (int)sizeof(float));
    cudaFuncSetAttribute(edge_kernel, cudaFuncAttributeMaxDynamicSharedMemorySize,
                         EK_SMEM_FLOATS * (int)sizeof(float));
    cudaFuncSetAttribute(node_kernel, cudaFuncAttributeMaxDynamicSharedMemorySize,
                         NK_SMEM_FLOATS * (int)sizeof(float));

    precompute_y_kernel<<<nsm, PY_NW * 32, PY_SMEM_FLOATS * sizeof(float)>>>(x, Wm1, ei);
    edge_kernel<<<nsm, EK_NW * 32, EK_SMEM_FLOATS * sizeof(float)>>>(
        ei, ea, Wm1, bm1, Wm2, bm2, Wt1, bt1, Wt2, bt2, e_out);
    node_kernel<<<2*nsm, NK_NW * 32, NK_SMEM_FLOATS * sizeof(float)>>>(
        x, Wu1, bu1, Wu2, bu2, x_out);
}